// round 3
// baseline (speedup 1.0000x reference)
#include <cuda_runtime.h>
#include <cuda_fp16.h>
#include <cstdint>
#include <cstring>

#define DN 256
#define DP 128
#define LSEQ 512
#define BATCH 2

__device__ float g_a[BATCH * LSEQ * DP];
__device__ float g_b[BATCH * LSEQ * DP];

// ---------------------------------------------------------------------------
// helpers
// ---------------------------------------------------------------------------
__device__ __forceinline__ uint32_t smem_u32(const void* p) {
    uint32_t a;
    asm("{ .reg .u64 t; cvta.to.shared.u64 t, %1; cvt.u32.u64 %0, t; }" : "=r"(a) : "l"(p));
    return a;
}
__device__ __forceinline__ uint32_t pack_half2(float x, float y) {
    __half2 h = __floats2half2_rn(x, y);
    uint32_t u;
    memcpy(&u, &h, 4);
    return u;
}
__device__ __forceinline__ void mma16816(float* c, uint32_t a0, uint32_t a1,
                                         uint32_t a2, uint32_t a3,
                                         uint32_t b0, uint32_t b1) {
    asm volatile(
        "mma.sync.aligned.m16n8k16.row.col.f32.f16.f16.f32 "
        "{%0,%1,%2,%3}, {%4,%5,%6,%7}, {%8,%9}, {%0,%1,%2,%3};"
        : "+f"(c[0]), "+f"(c[1]), "+f"(c[2]), "+f"(c[3])
        : "r"(a0), "r"(a1), "r"(a2), "r"(a3), "r"(b0), "r"(b1));
}
__device__ __forceinline__ void cp_async16(uint32_t dst, const void* src) {
    asm volatile("cp.async.cg.shared.global [%0], [%1], 16;" :: "r"(dst), "l"(src));
}
#define CP_COMMIT() asm volatile("cp.async.commit_group;" ::: "memory")
#define CP_WAIT0()  asm volatile("cp.async.wait_group 0;" ::: "memory")

// ---------------------------------------------------------------------------
// Kernel 1: LayerNorm(single) + a/b projections (fp32, small)
// ---------------------------------------------------------------------------
__global__ __launch_bounds__(256) void ab_kernel(
    const float* __restrict__ single, const float* __restrict__ ng,
    const float* __restrict__ nb, const float* __restrict__ Wa,
    const float* __restrict__ ba, const float* __restrict__ Wb,
    const float* __restrict__ bb)
{
    extern __shared__ float sm1[];
    float* xn = sm1;          // 8 x 256
    float* Ws = sm1 + 2048;   // 256 x 65 (padded)
    int tid = threadIdx.x, wid = tid >> 5, lane = tid & 31;

    int grow = blockIdx.x * 8 + wid;
    const float* x = single + grow * DN;
    float v[8], s = 0.f, sq = 0.f;
#pragma unroll
    for (int k = 0; k < 8; k++) { v[k] = x[lane + 32 * k]; s += v[k]; sq += v[k] * v[k]; }
#pragma unroll
    for (int o = 16; o > 0; o >>= 1) {
        s  += __shfl_xor_sync(0xFFFFFFFFu, s,  o);
        sq += __shfl_xor_sync(0xFFFFFFFFu, sq, o);
    }
    float mu = s * (1.f / DN);
    float rs = rsqrtf(sq * (1.f / DN) - mu * mu + 1e-5f);
#pragma unroll
    for (int k = 0; k < 8; k++) {
        int d = lane + 32 * k;
        xn[wid * DN + d] = (v[k] - mu) * rs * ng[d] + nb[d];
    }
    __syncthreads();

    float acc[8];
#pragma unroll
    for (int r = 0; r < 8; r++) acc[r] = 0.f;
    int c = tid;
    for (int ch = 0; ch < 4; ch++) {
        int d0 = ch * 64;
        __syncthreads();
        for (int e = tid; e < 16384; e += 256) {
            int cc = e >> 6, dc = e & 63;
            const float* src = (cc < DP) ? (Wa + cc * DN) : (Wb + (cc - DP) * DN);
            Ws[cc * 65 + dc] = src[d0 + dc];
        }
        __syncthreads();
#pragma unroll 4
        for (int dc = 0; dc < 64; dc++) {
            float w = Ws[c * 65 + dc];
            const float* xr = xn + d0 + dc;
#pragma unroll
            for (int r = 0; r < 8; r++) acc[r] += w * xr[r * DN];
        }
    }
    int row0 = blockIdx.x * 8;
    if (c < DP) {
        float bias = ba[c];
#pragma unroll
        for (int r = 0; r < 8; r++) g_a[(row0 + r) * DP + c] = acc[r] + bias;
    } else {
        float bias = bb[c - DP];
#pragma unroll
        for (int r = 0; r < 8; r++) g_b[(row0 + r) * DP + (c - DP)] = acc[r] + bias;
    }
}

// ---------------------------------------------------------------------------
// Kernel 2: fused outer-product + Wo GEMM (mma.sync fp16) + pair-add + LN
// tile = 128 rows (8 i x 16 j) x 128 outputs, K = 128
// warp layout: wm = wid/4 (2 m-groups of 64), wn = wid%4 (4 n-groups of 32)
// ---------------------------------------------------------------------------
#define LSTR 136   // L row stride in halves (272 B: conflict-free A-frag LDS)
#define USTR 132   // upd row stride in floats
#define SM_PAIR 0                 // 128*128*4 = 65536
#define SM_L    65536             // 128*136*2 = 34816
#define SM_A    100352            // 8*128*4   = 4096
#define SM_B    104448            // 16*128*4  = 8192 -> end 112640
#define SM_UPD  65536             // alias over L+a+b: 128*132*4 = 67584 -> end 133120
#define SM_TOTAL 133120

__global__ __launch_bounds__(256, 1) void pair_kernel(
    const float* __restrict__ pairp, const float* __restrict__ Wo,
    const float* __restrict__ bo, const float* __restrict__ pg,
    const float* __restrict__ pb, float* __restrict__ outp)
{
    extern __shared__ __align__(16) char smc[];
    uint32_t sbase = smem_u32(smc);
    float*  pair_s = (float*)(smc + SM_PAIR);
    __half* L_s    = (__half*)(smc + SM_L);
    float*  a_s    = (float*)(smc + SM_A);
    float*  b_s    = (float*)(smc + SM_B);
    float*  upd    = (float*)(smc + SM_UPD);

    int tid = threadIdx.x, wid = tid >> 5, lane = tid & 31;
    int wm = wid >> 2, wn = wid & 3;
    int g = lane >> 2, q = lane & 3;

    // --- W fragments in registers (persistent across tiles) ---
    uint32_t Breg[4][8][2];
    {
        int nbase = wn * 32 + g;
#pragma unroll
        for (int nt = 0; nt < 4; nt++) {
            const float* wrow = Wo + (nbase + nt * 8) * DP;
#pragma unroll
            for (int ks = 0; ks < 8; ks++) {
                int k = ks * 16 + q * 2;
                Breg[nt][ks][0] = pack_half2(wrow[k],     wrow[k + 1]);
                Breg[nt][ks][1] = pack_half2(wrow[k + 8], wrow[k + 9]);
            }
        }
    }
    float4 pgv = *(const float4*)(pg + lane * 4);
    float4 pbv = *(const float4*)(pb + lane * 4);
    float4 bov = *(const float4*)(bo + lane * 4);

    for (int tile = blockIdx.x; tile < 4096; tile += gridDim.x) {
        int bt  = tile >> 11;
        int rem = tile & 2047;
        int i0  = (rem >> 5) * 8;   // 64 i-tiles of 8
        int j0  = (rem & 31) * 16;  // 32 j-tiles of 16

        __syncthreads();  // previous epilogue done: pair_s / upd-alias free

        // --- prefetch pair tile via cp.async (warp w handles rows w*16..+15) ---
        {
#pragma unroll
            for (int r = 0; r < 16; r++) {
                int m = wid * 16 + r;
                int il = m & 7, jl = m >> 3;
                const float* src = pairp +
                    (((size_t)(bt * LSEQ + i0 + il)) * LSEQ + (j0 + jl)) * DP + lane * 4;
                uint32_t dst = sbase + SM_PAIR + (uint32_t)(m * DP + lane * 4) * 4u;
                cp_async16(dst, src);
            }
            CP_COMMIT();
        }

        // --- stage a (8x128) and b (16x128) in smem ---
        {
            const float4* ga = (const float4*)(g_a + (bt * LSEQ + i0) * DP);
            ((float4*)a_s)[tid] = ga[tid];
            const float4* gb = (const float4*)(g_b + (bt * LSEQ + j0) * DP);
            ((float4*)b_s)[tid]       = gb[tid];
            ((float4*)b_s)[tid + 256] = gb[tid + 256];
        }
        __syncthreads();

        // --- build L[m][d] = a_i[d] * b_j[d] as fp16 (m = jl*8 + il) ---
        {
            int row = tid >> 1, half = tid & 1;
            const float* ar = a_s + (row & 7) * DP + half * 64;
            const float* br = b_s + (row >> 3) * DP + half * 64;
            uint32_t* dst = (uint32_t*)(L_s + row * LSTR + half * 64);
#pragma unroll 8
            for (int d = 0; d < 64; d += 2)
                dst[d >> 1] = pack_half2(ar[d] * br[d], ar[d + 1] * br[d + 1]);
        }
        __syncthreads();

        // --- MMA: C[128x128] = L @ Wo^T ---
        float Cacc[4][4][4];
#pragma unroll
        for (int mt = 0; mt < 4; mt++)
#pragma unroll
            for (int nt = 0; nt < 4; nt++)
#pragma unroll
                for (int e = 0; e < 4; e++) Cacc[mt][nt][e] = 0.f;

#pragma unroll
        for (int ks = 0; ks < 8; ks++) {
            int k = ks * 16 + q * 2;
#pragma unroll
            for (int mt = 0; mt < 4; mt++) {
                const __half* Ab = L_s + (wm * 64 + mt * 16 + g) * LSTR + k;
                uint32_t a0 = *(const uint32_t*)(Ab);
                uint32_t a1 = *(const uint32_t*)(Ab + 8 * LSTR);
                uint32_t a2 = *(const uint32_t*)(Ab + 8);
                uint32_t a3 = *(const uint32_t*)(Ab + 8 * LSTR + 8);
#pragma unroll
                for (int nt = 0; nt < 4; nt++)
                    mma16816(Cacc[mt][nt], a0, a1, a2, a3,
                             Breg[nt][ks][0], Breg[nt][ks][1]);
            }
        }

        CP_WAIT0();          // pair tile landed
        __syncthreads();     // all warps done reading L (upd aliases it)

        // --- stage C in smem (row-major, LN axis contiguous) ---
#pragma unroll
        for (int mt = 0; mt < 4; mt++) {
            int r0 = wm * 64 + mt * 16 + g;
#pragma unroll
            for (int nt = 0; nt < 4; nt++) {
                int c0 = wn * 32 + nt * 8 + q * 2;
                float2 v0 = make_float2(Cacc[mt][nt][0], Cacc[mt][nt][1]);
                float2 v1 = make_float2(Cacc[mt][nt][2], Cacc[mt][nt][3]);
                *(float2*)(upd + r0 * USTR + c0)       = v0;
                *(float2*)(upd + (r0 + 8) * USTR + c0) = v1;
            }
        }
        __syncthreads();

        // --- epilogue: +bo, +pair, LayerNorm over DP=128, store ---
        const float rc = 1.f / 128.f;
#pragma unroll 1
        for (int kk = 0; kk < 16; kk++) {
            int row = wid * 16 + kk;
            int il = row & 7, jl = row >> 3;
            size_t gidx = (((size_t)(bt * LSEQ + i0 + il)) * LSEQ + (j0 + jl)) * DP;
            float4 pv = *((const float4*)(pair_s + row * DP) + lane);
            float4 uv = *((const float4*)(upd + row * USTR) + lane);
            float v0 = uv.x + bov.x + pv.x;
            float v1 = uv.y + bov.y + pv.y;
            float v2 = uv.z + bov.z + pv.z;
            float v3 = uv.w + bov.w + pv.w;
            float s = v0 + v1 + v2 + v3;
            float qq = v0 * v0 + v1 * v1 + v2 * v2 + v3 * v3;
#pragma unroll
            for (int o = 16; o > 0; o >>= 1) {
                s  += __shfl_xor_sync(0xFFFFFFFFu, s,  o);
                qq += __shfl_xor_sync(0xFFFFFFFFu, qq, o);
            }
            float mu = s * rc;
            float rstd = rsqrtf(qq * rc - mu * mu + 1e-5f);
            float4 ov;
            ov.x = (v0 - mu) * rstd * pgv.x + pbv.x;
            ov.y = (v1 - mu) * rstd * pgv.y + pbv.y;
            ov.z = (v2 - mu) * rstd * pgv.z + pbv.z;
            ov.w = (v3 - mu) * rstd * pgv.w + pbv.w;
            *((float4*)(outp + gidx) + lane) = ov;
        }
    }
}

// ---------------------------------------------------------------------------
// Host launcher
// ---------------------------------------------------------------------------
extern "C" void kernel_launch(void* const* d_in, const int* in_sizes, int n_in,
                              void* d_out, int out_size)
{
    const float* single = (const float*)d_in[0];
    const float* pairp  = (const float*)d_in[1];
    const float* ng     = (const float*)d_in[2];
    const float* nb     = (const float*)d_in[3];
    const float* Wa     = (const float*)d_in[4];
    const float* ba     = (const float*)d_in[5];
    const float* Wb     = (const float*)d_in[6];
    const float* bb     = (const float*)d_in[7];
    const float* Wo     = (const float*)d_in[8];
    const float* bo     = (const float*)d_in[9];
    const float* pg     = (const float*)d_in[10];
    const float* pb     = (const float*)d_in[11];
    float* outp = (float*)d_out;

    cudaFuncSetAttribute(ab_kernel, cudaFuncAttributeMaxDynamicSharedMemorySize, 74752);
    cudaFuncSetAttribute(pair_kernel, cudaFuncAttributeMaxDynamicSharedMemorySize, SM_TOTAL);

    ab_kernel<<<128, 256, 74752>>>(single, ng, nb, Wa, ba, Wb, bb);
    pair_kernel<<<148, 256, SM_TOTAL>>>(pairp, Wo, bo, pg, pb, outp);
}

// round 4
// speedup vs baseline: 1.2796x; 1.2796x over previous
#include <cuda_runtime.h>
#include <cuda_fp16.h>
#include <cstdint>
#include <cstring>

#define DN 256
#define DP 128
#define LSEQ 512
#define BATCH 2

__device__ float g_a[BATCH * LSEQ * DP];
__device__ float g_b[BATCH * LSEQ * DP];

// ---------------------------------------------------------------------------
// helpers
// ---------------------------------------------------------------------------
__device__ __forceinline__ uint32_t pack_half2(float x, float y) {
    __half2 h = __floats2half2_rn(x, y);
    uint32_t u;
    memcpy(&u, &h, 4);
    return u;
}
__device__ __forceinline__ void mma16816(float* c, uint32_t a0, uint32_t a1,
                                         uint32_t a2, uint32_t a3,
                                         uint32_t b0, uint32_t b1) {
    asm volatile(
        "mma.sync.aligned.m16n8k16.row.col.f32.f16.f16.f32 "
        "{%0,%1,%2,%3}, {%4,%5,%6,%7}, {%8,%9}, {%0,%1,%2,%3};"
        : "+f"(c[0]), "+f"(c[1]), "+f"(c[2]), "+f"(c[3])
        : "r"(a0), "r"(a1), "r"(a2), "r"(a3), "r"(b0), "r"(b1));
}

// ---------------------------------------------------------------------------
// Kernel 1: LayerNorm(single) + a/b projections
// ---------------------------------------------------------------------------
__global__ __launch_bounds__(256) void ab_kernel(
    const float* __restrict__ single, const float* __restrict__ ng,
    const float* __restrict__ nb, const float* __restrict__ Wa,
    const float* __restrict__ ba, const float* __restrict__ Wb,
    const float* __restrict__ bb)
{
    extern __shared__ float sm1[];
    float* xn = sm1;          // 8 x 256
    float* Ws = sm1 + 2048;   // 256 x 65 (padded)
    int tid = threadIdx.x, wid = tid >> 5, lane = tid & 31;

    int grow = blockIdx.x * 8 + wid;
    const float* x = single + grow * DN;
    float v[8], s = 0.f, sq = 0.f;
#pragma unroll
    for (int k = 0; k < 8; k++) { v[k] = x[lane + 32 * k]; s += v[k]; sq += v[k] * v[k]; }
#pragma unroll
    for (int o = 16; o > 0; o >>= 1) {
        s  += __shfl_xor_sync(0xFFFFFFFFu, s,  o);
        sq += __shfl_xor_sync(0xFFFFFFFFu, sq, o);
    }
    float mu = s * (1.f / DN);
    float rs = rsqrtf(sq * (1.f / DN) - mu * mu + 1e-5f);
#pragma unroll
    for (int k = 0; k < 8; k++) {
        int d = lane + 32 * k;
        xn[wid * DN + d] = (v[k] - mu) * rs * ng[d] + nb[d];
    }
    __syncthreads();

    float acc[8];
#pragma unroll
    for (int r = 0; r < 8; r++) acc[r] = 0.f;
    int c = tid;
    for (int ch = 0; ch < 4; ch++) {
        int d0 = ch * 64;
        __syncthreads();
        for (int e = tid; e < 16384; e += 256) {
            int cc = e >> 6, dc = e & 63;
            const float* src = (cc < DP) ? (Wa + cc * DN) : (Wb + (cc - DP) * DN);
            Ws[cc * 65 + dc] = src[d0 + dc];
        }
        __syncthreads();
#pragma unroll 4
        for (int dc = 0; dc < 64; dc++) {
            float w = Ws[c * 65 + dc];
            const float* xr = xn + d0 + dc;
#pragma unroll
            for (int r = 0; r < 8; r++) acc[r] += w * xr[r * DN];
        }
    }
    int row0 = blockIdx.x * 8;
    if (c < DP) {
        float bias = ba[c];
#pragma unroll
        for (int r = 0; r < 8; r++) g_a[(row0 + r) * DP + c] = acc[r] + bias;
    } else {
        float bias = bb[c - DP];
#pragma unroll
        for (int r = 0; r < 8; r++) g_b[(row0 + r) * DP + (c - DP)] = acc[r] + bias;
    }
}

// ---------------------------------------------------------------------------
// Kernel 2: fused outer-product + Wo GEMM (mma.sync fp16) + pair-add + LN
// 512 threads (16 warps), tile = 128 rows (8 i x 16 j) x 128 out, K = 128
// warps: wm = wid>>2 (4 m-groups of 32), wn = wid&3 (4 n-groups of 32)
// ---------------------------------------------------------------------------
#define WSTR 136   // Wo_s row stride in halves (conflict-free B LDS)
#define LSTR 136   // L_s row stride in halves (conflict-free A LDS)
#define SM_WO   0                  // 128*136*2 = 34816
#define SM_L    34816              // 128*136*2 = 34816
#define SM_PART 69632              // 4*128*8 (float2) = 4096
#define SM_TOTAL 73728

__global__ __launch_bounds__(512, 1) void pair_kernel(
    const float* __restrict__ pairp, const float* __restrict__ Wo,
    const float* __restrict__ bo, const float* __restrict__ pg,
    const float* __restrict__ pb, float* __restrict__ outp)
{
    extern __shared__ __align__(16) char smc[];
    __half* Wo_s = (__half*)(smc + SM_WO);
    __half* L_s  = (__half*)(smc + SM_L);
    float2* part = (float2*)(smc + SM_PART);

    int tid = threadIdx.x, wid = tid >> 5, lane = tid & 31;
    int wm = wid >> 2, wn = wid & 3;
    int g = lane >> 2, q = lane & 3;

    // --- stage Wo as fp16 in smem [n][k], stride WSTR ---
    for (int e = tid; e < DP * 64; e += 512) {
        int n = e >> 6;
        int d = (e & 63) * 2;
        float2 w = *(const float2*)(Wo + n * DP + d);
        *(uint32_t*)(Wo_s + n * WSTR + d) = pack_half2(w.x, w.y);
    }
    // --- per-thread epilogue constants at cols c(nt) = wn*32+nt*8+q*2 ---
    float2 bo2[4], pg2[4], pb2[4];
#pragma unroll
    for (int nt = 0; nt < 4; nt++) {
        int c0 = wn * 32 + nt * 8 + q * 2;
        bo2[nt] = *(const float2*)(bo + c0);
        pg2[nt] = *(const float2*)(pg + c0);
        pb2[nt] = *(const float2*)(pb + c0);
    }

    for (int tile = blockIdx.x; tile < 4096; tile += gridDim.x) {
        int bt  = tile >> 11;
        int rem = tile & 2047;
        int i0  = (rem >> 5) * 8;   // 64 i-tiles of 8
        int j0  = (rem & 31) * 16;  // 32 j-tiles of 16

        __syncthreads();  // prev MMA done reading L_s; part free

        // --- build L[m][d] = a_i[d]*b_j[d] fp16; m = jl*8+il; from global ---
        {
            int row = tid >> 2, qa = tid & 3;
            int il = row & 7, jl = row >> 3;
            const float4* ap = (const float4*)(g_a + (bt * LSEQ + i0 + il) * DP + qa * 32);
            const float4* bp = (const float4*)(g_b + (bt * LSEQ + j0 + jl) * DP + qa * 32);
            uint32_t* dst = (uint32_t*)(L_s + row * LSTR + qa * 32);
#pragma unroll
            for (int i = 0; i < 8; i++) {
                float4 av = ap[i];
                float4 bv = bp[i];
                uint2 h;
                h.x = pack_half2(av.x * bv.x, av.y * bv.y);
                h.y = pack_half2(av.z * bv.z, av.w * bv.w);
                *(uint2*)(dst + i * 2) = h;
            }
        }
        __syncthreads();

        // --- MMA: C[128x128] = L @ Wo^T, per-warp 32 rows x 32 cols ---
        float Cacc[2][4][4];
#pragma unroll
        for (int mt = 0; mt < 2; mt++)
#pragma unroll
            for (int nt = 0; nt < 4; nt++)
#pragma unroll
                for (int e = 0; e < 4; e++) Cacc[mt][nt][e] = 0.f;

#pragma unroll
        for (int ks = 0; ks < 8; ks++) {
            int k = ks * 16 + q * 2;
            uint32_t Bf[4][2];
#pragma unroll
            for (int nt = 0; nt < 4; nt++) {
                const __half* wr = Wo_s + (wn * 32 + nt * 8 + g) * WSTR + k;
                Bf[nt][0] = *(const uint32_t*)(wr);
                Bf[nt][1] = *(const uint32_t*)(wr + 8);
            }
#pragma unroll
            for (int mt = 0; mt < 2; mt++) {
                const __half* Ab = L_s + (wm * 32 + mt * 16 + g) * LSTR + k;
                uint32_t a0 = *(const uint32_t*)(Ab);
                uint32_t a1 = *(const uint32_t*)(Ab + 8 * LSTR);
                uint32_t a2 = *(const uint32_t*)(Ab + 8);
                uint32_t a3 = *(const uint32_t*)(Ab + 8 * LSTR + 8);
#pragma unroll
                for (int nt = 0; nt < 4; nt++)
                    mma16816(Cacc[mt][nt], a0, a1, a2, a3, Bf[nt][0], Bf[nt][1]);
            }
        }

        // --- epilogue pass 1: v = C + bo + pair (LDG direct); row partials ---
        float rs[4], rq[4];
#pragma unroll
        for (int t = 0; t < 4; t++) { rs[t] = 0.f; rq[t] = 0.f; }
        size_t gb[2][2];
#pragma unroll
        for (int mt = 0; mt < 2; mt++) {
            int r1 = wm * 32 + mt * 16 + g;
            int r2 = r1 + 8;
            gb[mt][0] = (((size_t)(bt * LSEQ + i0 + (r1 & 7))) * LSEQ + (j0 + (r1 >> 3))) * DP;
            gb[mt][1] = (((size_t)(bt * LSEQ + i0 + (r2 & 7))) * LSEQ + (j0 + (r2 >> 3))) * DP;
        }
#pragma unroll
        for (int mt = 0; mt < 2; mt++) {
#pragma unroll
            for (int nt = 0; nt < 4; nt++) {
                int c0 = wn * 32 + nt * 8 + q * 2;
                float2 p0 = *(const float2*)(pairp + gb[mt][0] + c0);
                float2 p1 = *(const float2*)(pairp + gb[mt][1] + c0);
                float* C = Cacc[mt][nt];
                float v0 = C[0] + bo2[nt].x + p0.x;
                float v1 = C[1] + bo2[nt].y + p0.y;
                float v2 = C[2] + bo2[nt].x + p1.x;
                float v3 = C[3] + bo2[nt].y + p1.y;
                C[0] = v0; C[1] = v1; C[2] = v2; C[3] = v3;
                rs[mt * 2]     += v0 + v1;
                rq[mt * 2]     += v0 * v0 + v1 * v1;
                rs[mt * 2 + 1] += v2 + v3;
                rq[mt * 2 + 1] += v2 * v2 + v3 * v3;
            }
        }
        // reduce over the 4 q-lanes (lane bits 0,1)
#pragma unroll
        for (int t = 0; t < 4; t++) {
            rs[t] += __shfl_xor_sync(0xFFFFFFFFu, rs[t], 1);
            rs[t] += __shfl_xor_sync(0xFFFFFFFFu, rs[t], 2);
            rq[t] += __shfl_xor_sync(0xFFFFFFFFu, rq[t], 1);
            rq[t] += __shfl_xor_sync(0xFFFFFFFFu, rq[t], 2);
        }
        if (q == 0) {
#pragma unroll
            for (int mt = 0; mt < 2; mt++) {
#pragma unroll
                for (int h = 0; h < 2; h++) {
                    int row = wm * 32 + mt * 16 + g + h * 8;
                    part[wn * 128 + row] = make_float2(rs[mt * 2 + h], rq[mt * 2 + h]);
                }
            }
        }
        __syncthreads();

        // --- LN params per row + pass 2: normalize + store ---
        const float rc = 1.f / 128.f;
        float mu[4], rstd[4];
#pragma unroll
        for (int mt = 0; mt < 2; mt++) {
#pragma unroll
            for (int h = 0; h < 2; h++) {
                int row = wm * 32 + mt * 16 + g + h * 8;
                float2 a0 = part[row];
                float2 a1 = part[128 + row];
                float2 a2 = part[256 + row];
                float2 a3 = part[384 + row];
                float ssum = a0.x + a1.x + a2.x + a3.x;
                float qsum = a0.y + a1.y + a2.y + a3.y;
                float m = ssum * rc;
                mu[mt * 2 + h] = m;
                rstd[mt * 2 + h] = rsqrtf(qsum * rc - m * m + 1e-5f);
            }
        }
#pragma unroll
        for (int mt = 0; mt < 2; mt++) {
#pragma unroll
            for (int nt = 0; nt < 4; nt++) {
                int c0 = wn * 32 + nt * 8 + q * 2;
                float* C = Cacc[mt][nt];
                float m0 = mu[mt * 2],     s0 = rstd[mt * 2];
                float m1 = mu[mt * 2 + 1], s1 = rstd[mt * 2 + 1];
                float2 o0, o1;
                o0.x = (C[0] - m0) * s0 * pg2[nt].x + pb2[nt].x;
                o0.y = (C[1] - m0) * s0 * pg2[nt].y + pb2[nt].y;
                o1.x = (C[2] - m1) * s1 * pg2[nt].x + pb2[nt].x;
                o1.y = (C[3] - m1) * s1 * pg2[nt].y + pb2[nt].y;
                *(float2*)(outp + gb[mt][0] + c0) = o0;
                *(float2*)(outp + gb[mt][1] + c0) = o1;
            }
        }
    }
}

// ---------------------------------------------------------------------------
// Host launcher
// ---------------------------------------------------------------------------
extern "C" void kernel_launch(void* const* d_in, const int* in_sizes, int n_in,
                              void* d_out, int out_size)
{
    const float* single = (const float*)d_in[0];
    const float* pairp  = (const float*)d_in[1];
    const float* ng     = (const float*)d_in[2];
    const float* nb     = (const float*)d_in[3];
    const float* Wa     = (const float*)d_in[4];
    const float* ba     = (const float*)d_in[5];
    const float* Wb     = (const float*)d_in[6];
    const float* bb     = (const float*)d_in[7];
    const float* Wo     = (const float*)d_in[8];
    const float* bo     = (const float*)d_in[9];
    const float* pg     = (const float*)d_in[10];
    const float* pb     = (const float*)d_in[11];
    float* outp = (float*)d_out;

    cudaFuncSetAttribute(ab_kernel, cudaFuncAttributeMaxDynamicSharedMemorySize, 74752);
    cudaFuncSetAttribute(pair_kernel, cudaFuncAttributeMaxDynamicSharedMemorySize, SM_TOTAL);

    ab_kernel<<<128, 256, 74752>>>(single, ng, nb, Wa, ba, Wb, bb);
    pair_kernel<<<148, 512, SM_TOTAL>>>(pairp, Wo, bo, pg, pb, outp);
}

// round 5
// speedup vs baseline: 1.9447x; 1.5198x over previous
#include <cuda_runtime.h>
#include <cuda_fp16.h>
#include <cstdint>
#include <cstring>

#define DN 256
#define DP 128
#define LSEQ 512
#define BATCH 2

__device__ float g_a[BATCH * LSEQ * DP];
__device__ float g_b[BATCH * LSEQ * DP];

// ---------------------------------------------------------------------------
// helpers
// ---------------------------------------------------------------------------
__device__ __forceinline__ uint32_t pack_half2(float x, float y) {
    __half2 h = __floats2half2_rn(x, y);
    uint32_t u;
    memcpy(&u, &h, 4);
    return u;
}
__device__ __forceinline__ void mma16816(float* c, uint32_t a0, uint32_t a1,
                                         uint32_t a2, uint32_t a3,
                                         uint32_t b0, uint32_t b1) {
    asm volatile(
        "mma.sync.aligned.m16n8k16.row.col.f32.f16.f16.f32 "
        "{%0,%1,%2,%3}, {%4,%5,%6,%7}, {%8,%9}, {%0,%1,%2,%3};"
        : "+f"(c[0]), "+f"(c[1]), "+f"(c[2]), "+f"(c[3])
        : "r"(a0), "r"(a1), "r"(a2), "r"(a3), "r"(b0), "r"(b1));
}

// ---------------------------------------------------------------------------
// Kernel 1: LayerNorm(single) + a/b projections
// ---------------------------------------------------------------------------
__global__ __launch_bounds__(256) void ab_kernel(
    const float* __restrict__ single, const float* __restrict__ ng,
    const float* __restrict__ nb, const float* __restrict__ Wa,
    const float* __restrict__ ba, const float* __restrict__ Wb,
    const float* __restrict__ bb)
{
    extern __shared__ float sm1[];
    float* xn = sm1;          // 8 x 256
    float* Ws = sm1 + 2048;   // 256 x 65 (padded)
    int tid = threadIdx.x, wid = tid >> 5, lane = tid & 31;

    int grow = blockIdx.x * 8 + wid;
    const float* x = single + grow * DN;
    float v[8], s = 0.f, sq = 0.f;
#pragma unroll
    for (int k = 0; k < 8; k++) { v[k] = x[lane + 32 * k]; s += v[k]; sq += v[k] * v[k]; }
#pragma unroll
    for (int o = 16; o > 0; o >>= 1) {
        s  += __shfl_xor_sync(0xFFFFFFFFu, s,  o);
        sq += __shfl_xor_sync(0xFFFFFFFFu, sq, o);
    }
    float mu = s * (1.f / DN);
    float rs = rsqrtf(sq * (1.f / DN) - mu * mu + 1e-5f);
#pragma unroll
    for (int k = 0; k < 8; k++) {
        int d = lane + 32 * k;
        xn[wid * DN + d] = (v[k] - mu) * rs * ng[d] + nb[d];
    }
    __syncthreads();

    float acc[8];
#pragma unroll
    for (int r = 0; r < 8; r++) acc[r] = 0.f;
    int c = tid;
    for (int ch = 0; ch < 4; ch++) {
        int d0 = ch * 64;
        __syncthreads();
        for (int e = tid; e < 16384; e += 256) {
            int cc = e >> 6, dc = e & 63;
            const float* src = (cc < DP) ? (Wa + cc * DN) : (Wb + (cc - DP) * DN);
            Ws[cc * 65 + dc] = src[d0 + dc];
        }
        __syncthreads();
#pragma unroll 4
        for (int dc = 0; dc < 64; dc++) {
            float w = Ws[c * 65 + dc];
            const float* xr = xn + d0 + dc;
#pragma unroll
            for (int r = 0; r < 8; r++) acc[r] += w * xr[r * DN];
        }
    }
    int row0 = blockIdx.x * 8;
    if (c < DP) {
        float bias = ba[c];
#pragma unroll
        for (int r = 0; r < 8; r++) g_a[(row0 + r) * DP + c] = acc[r] + bias;
    } else {
        float bias = bb[c - DP];
#pragma unroll
        for (int r = 0; r < 8; r++) g_b[(row0 + r) * DP + (c - DP)] = acc[r] + bias;
    }
}

// ---------------------------------------------------------------------------
// Kernel 2: fused outer-product + Wo GEMM (mma.sync fp16) + pair-add + LN
// 512 threads (16 warps), tile = 128 rows (8 i x 16 j) x 128 out, K = 128
// MMA warps: wm = wid>>2 (4 m-groups of 32), wn = wid&3 (4 n-groups of 32)
// Epilogue: warp w owns C rows 8w..8w+7 (full rows, coalesced)
// ---------------------------------------------------------------------------
#define WSTR 136   // Wo_s row stride in halves
#define LSTR 136   // L_s row stride in halves
#define CSTR 132   // Cs row stride in floats
#define SM_WO   0                  // 128*136*2 = 34816
#define SM_L    34816              // 128*136*2 = 34816
#define SM_C    69632              // 128*132*4 = 67584
#define SM_TOTAL 137216

__global__ __launch_bounds__(512, 1) void pair_kernel(
    const float* __restrict__ pairp, const float* __restrict__ Wo,
    const float* __restrict__ bo, const float* __restrict__ pg,
    const float* __restrict__ pb, float* __restrict__ outp)
{
    extern __shared__ __align__(16) char smc[];
    __half* Wo_s = (__half*)(smc + SM_WO);
    __half* L_s  = (__half*)(smc + SM_L);
    float*  Cs   = (float*)(smc + SM_C);

    int tid = threadIdx.x, wid = tid >> 5, lane = tid & 31;
    int wm = wid >> 2, wn = wid & 3;
    int g = lane >> 2, q = lane & 3;

    // --- stage Wo as fp16 in smem [n][k] ---
    for (int e = tid; e < DP * 64; e += 512) {
        int n = e >> 6;
        int d = (e & 63) * 2;
        float2 w = *(const float2*)(Wo + n * DP + d);
        *(uint32_t*)(Wo_s + n * WSTR + d) = pack_half2(w.x, w.y);
    }
    // --- per-lane epilogue constants (cols lane*4..lane*4+3) ---
    float4 bo4 = *(const float4*)(bo + lane * 4);
    float4 pg4 = *(const float4*)(pg + lane * 4);
    float4 pb4 = *(const float4*)(pb + lane * 4);

    for (int tile = blockIdx.x; tile < 4096; tile += gridDim.x) {
        int bt  = tile >> 11;
        int rem = tile & 2047;
        int i0  = (rem >> 5) * 8;   // 64 i-tiles of 8
        int j0  = (rem & 31) * 16;  // 32 j-tiles of 16

        __syncthreads();  // prev epilogue done with Cs; prev MMA done with L_s

        // --- build L[m][:] = a_{i0+(m&7)} * b_{j0+(m>>3)}; warp w: jl = w ---
        {
            const float4 bv = ((const float4*)(g_b + (size_t)(bt * LSEQ + j0 + wid) * DP))[lane];
#pragma unroll
            for (int r = 0; r < 8; r++) {
                float4 av = ((const float4*)(g_a + (size_t)(bt * LSEQ + i0 + r) * DP))[lane];
                uint2 h;
                h.x = pack_half2(av.x * bv.x, av.y * bv.y);
                h.y = pack_half2(av.z * bv.z, av.w * bv.w);
                *(uint2*)(L_s + (wid * 8 + r) * LSTR + lane * 4) = h;
            }
        }
        __syncthreads();

        // --- MMA: C[128x128] = L @ Wo^T, per-warp 32 rows x 32 cols ---
        float Cacc[2][4][4];
#pragma unroll
        for (int mt = 0; mt < 2; mt++)
#pragma unroll
            for (int nt = 0; nt < 4; nt++)
#pragma unroll
                for (int e = 0; e < 4; e++) Cacc[mt][nt][e] = 0.f;

#pragma unroll
        for (int ks = 0; ks < 8; ks++) {
            int k = ks * 16 + q * 2;
            uint32_t Bf[4][2];
#pragma unroll
            for (int nt = 0; nt < 4; nt++) {
                const __half* wr = Wo_s + (wn * 32 + nt * 8 + g) * WSTR + k;
                Bf[nt][0] = *(const uint32_t*)(wr);
                Bf[nt][1] = *(const uint32_t*)(wr + 8);
            }
#pragma unroll
            for (int mt = 0; mt < 2; mt++) {
                const __half* Ab = L_s + (wm * 32 + mt * 16 + g) * LSTR + k;
                uint32_t a0 = *(const uint32_t*)(Ab);
                uint32_t a1 = *(const uint32_t*)(Ab + 8 * LSTR);
                uint32_t a2 = *(const uint32_t*)(Ab + 8);
                uint32_t a3 = *(const uint32_t*)(Ab + 8 * LSTR + 8);
#pragma unroll
                for (int nt = 0; nt < 4; nt++)
                    mma16816(Cacc[mt][nt], a0, a1, a2, a3, Bf[nt][0], Bf[nt][1]);
            }
        }

        // --- stage C fragments into Cs ---
#pragma unroll
        for (int mt = 0; mt < 2; mt++) {
            int r1 = wm * 32 + mt * 16 + g;
#pragma unroll
            for (int nt = 0; nt < 4; nt++) {
                int c0 = wn * 32 + nt * 8 + q * 2;
                *(float2*)(Cs + r1 * CSTR + c0)       = make_float2(Cacc[mt][nt][0], Cacc[mt][nt][1]);
                *(float2*)(Cs + (r1 + 8) * CSTR + c0) = make_float2(Cacc[mt][nt][2], Cacc[mt][nt][3]);
            }
        }

        // --- prefetch pair rows (coalesced float4) while STS drains ---
        float4 pv[8];
        size_t gaddr[8];
#pragma unroll
        for (int r = 0; r < 8; r++) {
            int m = wid * 8 + r;
            int il = m & 7, jl = m >> 3;
            gaddr[r] = (((size_t)(bt * LSEQ + i0 + il)) * LSEQ + (j0 + jl)) * DP;
            pv[r] = *((const float4*)(pairp + gaddr[r]) + lane);
        }
        __syncthreads();

        // --- epilogue: warp w owns rows 8w..8w+7; full-row LN ---
        const float rc = 1.f / 128.f;
#pragma unroll
        for (int r = 0; r < 8; r++) {
            int m = wid * 8 + r;
            float4 cv = *((const float4*)(Cs + m * CSTR) + lane);
            float v0 = cv.x + bo4.x + pv[r].x;
            float v1 = cv.y + bo4.y + pv[r].y;
            float v2 = cv.z + bo4.z + pv[r].z;
            float v3 = cv.w + bo4.w + pv[r].w;
            float s  = v0 + v1 + v2 + v3;
            float qq = v0 * v0 + v1 * v1 + v2 * v2 + v3 * v3;
#pragma unroll
            for (int o = 16; o > 0; o >>= 1) {
                s  += __shfl_xor_sync(0xFFFFFFFFu, s,  o);
                qq += __shfl_xor_sync(0xFFFFFFFFu, qq, o);
            }
            float mu = s * rc;
            float rstd = rsqrtf(qq * rc - mu * mu + 1e-5f);
            float4 ov;
            ov.x = (v0 - mu) * rstd * pg4.x + pb4.x;
            ov.y = (v1 - mu) * rstd * pg4.y + pb4.y;
            ov.z = (v2 - mu) * rstd * pg4.z + pb4.z;
            ov.w = (v3 - mu) * rstd * pg4.w + pb4.w;
            *((float4*)(outp + gaddr[r]) + lane) = ov;
        }
    }
}

// ---------------------------------------------------------------------------
// Host launcher
// ---------------------------------------------------------------------------
extern "C" void kernel_launch(void* const* d_in, const int* in_sizes, int n_in,
                              void* d_out, int out_size)
{
    const float* single = (const float*)d_in[0];
    const float* pairp  = (const float*)d_in[1];
    const float* ng     = (const float*)d_in[2];
    const float* nb     = (const float*)d_in[3];
    const float* Wa     = (const float*)d_in[4];
    const float* ba     = (const float*)d_in[5];
    const float* Wb     = (const float*)d_in[6];
    const float* bb     = (const float*)d_in[7];
    const float* Wo     = (const float*)d_in[8];
    const float* bo     = (const float*)d_in[9];
    const float* pg     = (const float*)d_in[10];
    const float* pb     = (const float*)d_in[11];
    float* outp = (float*)d_out;

    cudaFuncSetAttribute(ab_kernel, cudaFuncAttributeMaxDynamicSharedMemorySize, 74752);
    cudaFuncSetAttribute(pair_kernel, cudaFuncAttributeMaxDynamicSharedMemorySize, SM_TOTAL);

    ab_kernel<<<128, 256, 74752>>>(single, ng, nb, Wa, ba, Wb, bb);
    pair_kernel<<<148, 512, SM_TOTAL>>>(pairp, Wo, bo, pg, pb, outp);
}

// round 6
// speedup vs baseline: 2.0425x; 1.0503x over previous
#include <cuda_runtime.h>
#include <cuda_fp16.h>
#include <cstdint>
#include <cstring>

#define DN 256
#define DP 128
#define LSEQ 512
#define BATCH 2

__device__ float g_a[BATCH * LSEQ * DP];
__device__ float g_b[BATCH * LSEQ * DP];

// ---------------------------------------------------------------------------
// helpers
// ---------------------------------------------------------------------------
__device__ __forceinline__ uint32_t pack_half2(float x, float y) {
    __half2 h = __floats2half2_rn(x, y);
    uint32_t u;
    memcpy(&u, &h, 4);
    return u;
}
__device__ __forceinline__ void mma16816(float* c, uint32_t a0, uint32_t a1,
                                         uint32_t a2, uint32_t a3,
                                         uint32_t b0, uint32_t b1) {
    asm volatile(
        "mma.sync.aligned.m16n8k16.row.col.f32.f16.f16.f32 "
        "{%0,%1,%2,%3}, {%4,%5,%6,%7}, {%8,%9}, {%0,%1,%2,%3};"
        : "+f"(c[0]), "+f"(c[1]), "+f"(c[2]), "+f"(c[3])
        : "r"(a0), "r"(a1), "r"(a2), "r"(a3), "r"(b0), "r"(b1));
}

// ---------------------------------------------------------------------------
// Kernel 1: LayerNorm(single) + a/b projections (float4-vectorized)
// 256 threads, 8 rows/CTA; thread = output column c (0..255)
// ---------------------------------------------------------------------------
#define WS_STR 68   // Ws row stride in floats (16B-aligned, conflict-free)

__global__ __launch_bounds__(256) void ab_kernel(
    const float* __restrict__ single, const float* __restrict__ ng,
    const float* __restrict__ nb, const float* __restrict__ Wa,
    const float* __restrict__ ba, const float* __restrict__ Wb,
    const float* __restrict__ bb)
{
    extern __shared__ float sm1[];
    float* xn = sm1;          // 8 x 256
    float* Ws = sm1 + 2048;   // 256 x 68
    int tid = threadIdx.x, wid = tid >> 5, lane = tid & 31;

    int grow = blockIdx.x * 8 + wid;
    const float* x = single + grow * DN;
    float v[8], s = 0.f, sq = 0.f;
#pragma unroll
    for (int k = 0; k < 8; k++) { v[k] = x[lane + 32 * k]; s += v[k]; sq += v[k] * v[k]; }
#pragma unroll
    for (int o = 16; o > 0; o >>= 1) {
        s  += __shfl_xor_sync(0xFFFFFFFFu, s,  o);
        sq += __shfl_xor_sync(0xFFFFFFFFu, sq, o);
    }
    float mu = s * (1.f / DN);
    float rs = rsqrtf(sq * (1.f / DN) - mu * mu + 1e-5f);
#pragma unroll
    for (int k = 0; k < 8; k++) {
        int d = lane + 32 * k;
        xn[wid * DN + d] = (v[k] - mu) * rs * ng[d] + nb[d];
    }
    __syncthreads();

    float acc[8];
#pragma unroll
    for (int r = 0; r < 8; r++) acc[r] = 0.f;
    int c = tid;
    for (int ch = 0; ch < 4; ch++) {
        int d0 = ch * 64;
        for (int e = tid; e < 16384; e += 256) {
            int cc = e >> 6, dc = e & 63;
            const float* src = (cc < DP) ? (Wa + cc * DN) : (Wb + (cc - DP) * DN);
            Ws[cc * WS_STR + dc] = src[d0 + dc];
        }
        __syncthreads();
#pragma unroll 2
        for (int dg = 0; dg < 16; dg++) {
            float4 w4 = *(const float4*)(Ws + c * WS_STR + dg * 4);
#pragma unroll
            for (int r = 0; r < 8; r++) {
                float4 x4 = *(const float4*)(xn + r * DN + d0 + dg * 4);
                acc[r] += w4.x * x4.x + w4.y * x4.y + w4.z * x4.z + w4.w * x4.w;
            }
        }
        __syncthreads();
    }
    int row0 = blockIdx.x * 8;
    if (c < DP) {
        float bias = ba[c];
#pragma unroll
        for (int r = 0; r < 8; r++) g_a[(row0 + r) * DP + c] = acc[r] + bias;
    } else {
        float bias = bb[c - DP];
#pragma unroll
        for (int r = 0; r < 8; r++) g_b[(row0 + r) * DP + (c - DP)] = acc[r] + bias;
    }
}

// ---------------------------------------------------------------------------
// Kernel 2: fused outer-product + Wo GEMM (mma.sync fp16) + pair-add + LN
// 512 threads (16 warps), tile = 128 rows (8 i x 16 j) x 128 out, K = 128
// Double-buffered L_s; 2 syncs/tile; build(next) overlaps epilogue(cur)
// ---------------------------------------------------------------------------
#define WSTR 136   // Wo_s row stride in halves
#define LSTR 136   // L_s row stride in halves
#define CSTR 136   // Cs row stride in floats (conflict-free STS.64 + LDS.128)
#define SM_WO   0                  // 128*136*2 = 34816
#define SM_L0   34816              // 34816
#define SM_L1   69632              // 34816
#define SM_C    104448             // 128*136*4 = 69632
#define SM_TOTAL 174080

__global__ __launch_bounds__(512, 1) void pair_kernel(
    const float* __restrict__ pairp, const float* __restrict__ Wo,
    const float* __restrict__ bo, const float* __restrict__ pg,
    const float* __restrict__ pb, float* __restrict__ outp)
{
    extern __shared__ __align__(16) char smc[];
    __half* Wo_s = (__half*)(smc + SM_WO);
    float*  Cs   = (float*)(smc + SM_C);

    int tid = threadIdx.x, wid = tid >> 5, lane = tid & 31;
    int wm = wid >> 2, wn = wid & 3;
    int g = lane >> 2, q = lane & 3;

    // --- stage Wo as fp16 in smem [n][k] ---
    for (int e = tid; e < DP * 64; e += 512) {
        int n = e >> 6;
        int d = (e & 63) * 2;
        float2 w = *(const float2*)(Wo + n * DP + d);
        *(uint32_t*)(Wo_s + n * WSTR + d) = pack_half2(w.x, w.y);
    }
    // --- per-lane epilogue constants (cols lane*4..lane*4+3) ---
    float4 bo4 = *(const float4*)(bo + lane * 4);
    float4 pg4 = *(const float4*)(pg + lane * 4);
    float4 pb4 = *(const float4*)(pb + lane * 4);

    // build L rows for a tile into the given buffer (warp w owns rows 8w..8w+7)
    auto build = [&](int t, __half* Lb) {
        int bt  = t >> 11;
        int rem = t & 2047;
        int bi0 = (rem >> 5) * 8;
        int bj0 = (rem & 31) * 16;
        const float4 bv = ((const float4*)(g_b + (size_t)(bt * LSEQ + bj0 + wid) * DP))[lane];
#pragma unroll
        for (int r = 0; r < 8; r++) {
            float4 av = ((const float4*)(g_a + (size_t)(bt * LSEQ + bi0 + r) * DP))[lane];
            uint2 h;
            h.x = pack_half2(av.x * bv.x, av.y * bv.y);
            h.y = pack_half2(av.z * bv.z, av.w * bv.w);
            *(uint2*)(Lb + (wid * 8 + r) * LSTR + lane * 4) = h;
        }
    };

    int tile = blockIdx.x;
    if (tile < 4096) build(tile, (__half*)(smc + SM_L0));
    __syncthreads();

    int p = 0;
    for (; tile < 4096; tile += gridDim.x) {
        int bt  = tile >> 11;
        int rem = tile & 2047;
        int i0  = (rem >> 5) * 8;
        int j0  = (rem & 31) * 16;
        __half* Lc = (__half*)(smc + (p ? SM_L1 : SM_L0));
        __half* Ln = (__half*)(smc + (p ? SM_L0 : SM_L1));

        // --- prefetch pair rows (DRAM; overlaps MMA) ---
        float4 pv[8];
        size_t gaddr[8];
#pragma unroll
        for (int r = 0; r < 8; r++) {
            int m = wid * 8 + r;
            int il = m & 7, jl = m >> 3;
            gaddr[r] = (((size_t)(bt * LSEQ + i0 + il)) * LSEQ + (j0 + jl)) * DP;
            pv[r] = *((const float4*)(pairp + gaddr[r]) + lane);
        }

        // --- MMA: C[128x128] = L @ Wo^T, per-warp 32 rows x 32 cols ---
        float Cacc[2][4][4];
#pragma unroll
        for (int mt = 0; mt < 2; mt++)
#pragma unroll
            for (int nt = 0; nt < 4; nt++)
#pragma unroll
                for (int e = 0; e < 4; e++) Cacc[mt][nt][e] = 0.f;

#pragma unroll
        for (int ks = 0; ks < 8; ks++) {
            int k = ks * 16 + q * 2;
            uint32_t Bf[4][2];
#pragma unroll
            for (int nt = 0; nt < 4; nt++) {
                const __half* wr = Wo_s + (wn * 32 + nt * 8 + g) * WSTR + k;
                Bf[nt][0] = *(const uint32_t*)(wr);
                Bf[nt][1] = *(const uint32_t*)(wr + 8);
            }
#pragma unroll
            for (int mt = 0; mt < 2; mt++) {
                const __half* Ab = Lc + (wm * 32 + mt * 16 + g) * LSTR + k;
                uint32_t a0 = *(const uint32_t*)(Ab);
                uint32_t a1 = *(const uint32_t*)(Ab + 8 * LSTR);
                uint32_t a2 = *(const uint32_t*)(Ab + 8);
                uint32_t a3 = *(const uint32_t*)(Ab + 8 * LSTR + 8);
#pragma unroll
                for (int nt = 0; nt < 4; nt++)
                    mma16816(Cacc[mt][nt], a0, a1, a2, a3, Bf[nt][0], Bf[nt][1]);
            }
        }

        // --- stage C fragments into Cs (conflict-free with CSTR=136) ---
#pragma unroll
        for (int mt = 0; mt < 2; mt++) {
            int r1 = wm * 32 + mt * 16 + g;
#pragma unroll
            for (int nt = 0; nt < 4; nt++) {
                int c0 = wn * 32 + nt * 8 + q * 2;
                *(float2*)(Cs + r1 * CSTR + c0)       = make_float2(Cacc[mt][nt][0], Cacc[mt][nt][1]);
                *(float2*)(Cs + (r1 + 8) * CSTR + c0) = make_float2(Cacc[mt][nt][2], Cacc[mt][nt][3]);
            }
        }
        __syncthreads();   // Cs visible; L[cur] free for rewrite next iter

        // --- build next tile's L (overlaps epilogue below) ---
        int nxt = tile + gridDim.x;
        if (nxt < 4096) build(nxt, Ln);

        // --- epilogue: warp w owns rows 8w..8w+7; full-row LN ---
        const float rc = 1.f / 128.f;
#pragma unroll
        for (int r = 0; r < 8; r++) {
            int m = wid * 8 + r;
            float4 cv = *((const float4*)(Cs + m * CSTR) + lane);
            float v0 = cv.x + bo4.x + pv[r].x;
            float v1 = cv.y + bo4.y + pv[r].y;
            float v2 = cv.z + bo4.z + pv[r].z;
            float v3 = cv.w + bo4.w + pv[r].w;
            float s  = v0 + v1 + v2 + v3;
            float qq = v0 * v0 + v1 * v1 + v2 * v2 + v3 * v3;
#pragma unroll
            for (int o = 16; o > 0; o >>= 1) {
                s  += __shfl_xor_sync(0xFFFFFFFFu, s,  o);
                qq += __shfl_xor_sync(0xFFFFFFFFu, qq, o);
            }
            float mu = s * rc;
            float rstd = rsqrtf(qq * rc - mu * mu + 1e-5f);
            float4 ov;
            ov.x = (v0 - mu) * rstd * pg4.x + pb4.x;
            ov.y = (v1 - mu) * rstd * pg4.y + pb4.y;
            ov.z = (v2 - mu) * rstd * pg4.z + pb4.z;
            ov.w = (v3 - mu) * rstd * pg4.w + pb4.w;
            *((float4*)(outp + gaddr[r]) + lane) = ov;
        }
        __syncthreads();   // L[nxt] ready for all warps; Cs free
        p ^= 1;
    }
}

// ---------------------------------------------------------------------------
// Host launcher
// ---------------------------------------------------------------------------
extern "C" void kernel_launch(void* const* d_in, const int* in_sizes, int n_in,
                              void* d_out, int out_size)
{
    const float* single = (const float*)d_in[0];
    const float* pairp  = (const float*)d_in[1];
    const float* ng     = (const float*)d_in[2];
    const float* nb     = (const float*)d_in[3];
    const float* Wa     = (const float*)d_in[4];
    const float* ba     = (const float*)d_in[5];
    const float* Wb     = (const float*)d_in[6];
    const float* bb     = (const float*)d_in[7];
    const float* Wo     = (const float*)d_in[8];
    const float* bo     = (const float*)d_in[9];
    const float* pg     = (const float*)d_in[10];
    const float* pb     = (const float*)d_in[11];
    float* outp = (float*)d_out;

    cudaFuncSetAttribute(ab_kernel, cudaFuncAttributeMaxDynamicSharedMemorySize, 77824);
    cudaFuncSetAttribute(pair_kernel, cudaFuncAttributeMaxDynamicSharedMemorySize, SM_TOTAL);

    ab_kernel<<<128, 256, 77824>>>(single, ng, nb, Wa, ba, Wb, bb);
    pair_kernel<<<148, 512, SM_TOTAL>>>(pairp, Wo, bo, pg, pb, outp);
}